// round 10
// baseline (speedup 1.0000x reference)
#include <cuda_runtime.h>
#include <cuda.h>

#define NNODES 20000
#define DDIM   128
#define KNEI   32
#define ROWS   64            // rows per main block = 2 nodes * 32 neighbors
#define NBLK   (NNODES / 2)  // 10000 main blocks
#define STRIDE 132           // pre_kernel padded stride (unchanged)
#define WSTRIDE 136          // main kernel W stride: 136%32==8 -> conflict-free B frags

// ---- main-kernel smem layout (floats) ----
#define TILE_OFF 17408                     // after W (128*136)
#define STAGE_SZ 16384                     // link(8192) + neigh(8192) per stage
#define GSM_OFF  (TILE_OFF + 2*STAGE_SZ)   // 50176
#define GLW_OFF  (GSM_OFF + 64)            // 50240
#define GNW_OFF  (GLW_OFF + 128)           // 50368
#define BAR_OFF  (GNW_OFF + 128)           // 50496 (byte 201984, 8B aligned)
#define SMEM_FLOATS (BAR_OFF + 4)          // 50500 floats = 202000 bytes

// ---------------- scratch (device globals; no allocation) ----------------
__device__ float g_tsf[(size_t)NNODES * DDIM];  // self_feats @ self_weights
__device__ float g_ts[NNODES];                  // self_vecs . gate_self_w

// ---------------- helpers ----------------
__device__ __forceinline__ void cp_async16(float* smem_dst, const float* gmem_src) {
    unsigned s = (unsigned)__cvta_generic_to_shared(smem_dst);
    asm volatile("cp.async.cg.shared.global [%0], [%1], 16;\n" :: "r"(s), "l"(gmem_src));
}
#define CP_COMMIT() asm volatile("cp.async.commit_group;\n")
#define CP_WAIT(n)  asm volatile("cp.async.wait_group %0;\n" :: "n"(n))

__device__ __forceinline__ float tf32r(float x) {
    unsigned u;
    asm("cvt.rna.tf32.f32 %0, %1;" : "=r"(u) : "f"(x));
    return __uint_as_float(u);
}
__device__ __forceinline__ unsigned tf32u(float x) {
    unsigned u;
    asm("cvt.rna.tf32.f32 %0, %1;" : "=r"(u) : "f"(x));
    return u;
}

__device__ __forceinline__ void mma8(float c[4], const unsigned a[4], unsigned b0, unsigned b1) {
    asm volatile(
        "mma.sync.aligned.m16n8k8.row.col.f32.tf32.tf32.f32 "
        "{%0,%1,%2,%3}, {%4,%5,%6,%7}, {%8,%9}, {%0,%1,%2,%3};\n"
        : "+f"(c[0]), "+f"(c[1]), "+f"(c[2]), "+f"(c[3])
        : "r"(a[0]), "r"(a[1]), "r"(a[2]), "r"(a[3]), "r"(b0), "r"(b1));
}

__device__ __forceinline__ float sigm(float x) { return 1.f / (1.f + __expf(-x)); }

// swizzled SW128 tile accessor: tile = 4 boxes of [64 rows x 32 floats], 8KB each
__device__ __forceinline__ const float* swz(const float* base, int r, int c) {
    int off = ((c & 96) << 8)                                   // box * 8192 bytes
            + ((r * 128 + (c & 31) * 4) ^ ((r & 7) << 4));      // SW128 within box
    return (const float*)((const char*)base + off);
}

// ---------------- mbarrier + TMA ----------------
__device__ __forceinline__ void mbar_init(void* bar, unsigned count) {
    unsigned a = (unsigned)__cvta_generic_to_shared(bar);
    asm volatile("mbarrier.init.shared.b64 [%0], %1;" :: "r"(a), "r"(count) : "memory");
}
__device__ __forceinline__ void mbar_expect(void* bar, unsigned bytes) {
    unsigned a = (unsigned)__cvta_generic_to_shared(bar);
    asm volatile("mbarrier.arrive.expect_tx.shared.b64 _, [%0], %1;" :: "r"(a), "r"(bytes) : "memory");
}
__device__ __forceinline__ void mbar_wait(void* bar, unsigned parity) {
    unsigned a = (unsigned)__cvta_generic_to_shared(bar);
    asm volatile(
        "{\n\t.reg .pred P%=;\n"
        "LW%=:\n\t"
        "mbarrier.try_wait.parity.acquire.cta.shared::cta.b64 P%=, [%0], %1, 0x989680;\n\t"
        "@P%= bra LD%=;\n\t"
        "bra LW%=;\n"
        "LD%=:\n\t}"
        :: "r"(a), "r"(parity) : "memory");
}
__device__ __forceinline__ void tma2d(void* smem_dst, const CUtensorMap* map,
                                      int x, int y, void* bar) {
    unsigned d = (unsigned)__cvta_generic_to_shared(smem_dst);
    unsigned b = (unsigned)__cvta_generic_to_shared(bar);
    asm volatile(
        "cp.async.bulk.tensor.2d.shared::cta.global.tile.mbarrier::complete_tx::bytes "
        "[%0], [%1, {%2, %3}], [%4];"
        :: "r"(d), "l"(map), "r"(x), "r"(y), "r"(b) : "memory");
}

// ---------------- precompute: g_tsf = sf @ SW  (tf32 mma), g_ts = sv . gsw ----------------
__global__ void __launch_bounds__(256, 1)
pre_kernel(const float* __restrict__ sf, const float* __restrict__ sv,
           const float* __restrict__ gsw_g, const float* __restrict__ sw)
{
    extern __shared__ float sm[];
    float* SWs = sm;
    float* As  = sm + 16896;
    float* gsw = sm + 33792;
    const int tid = threadIdx.x;
    const int n0  = blockIdx.x * 128;

    for (int i = tid; i < 128 * 32; i += 256) {
        int r = i >> 5, c4 = (i & 31) << 2;
        cp_async16(SWs + r * STRIDE + c4, sw + r * DDIM + c4);
    }
    for (int i = tid; i < 128 * 32; i += 256) {
        int r = i >> 5, c4 = (i & 31) << 2;
        int n = n0 + r; if (n > NNODES - 1) n = NNODES - 1;
        cp_async16(As + r * STRIDE + c4, sf + (size_t)n * DDIM + c4);
    }
    if (tid < 32) cp_async16(gsw + tid * 4, gsw_g + tid * 4);
    CP_COMMIT();
    CP_WAIT(0);
    __syncthreads();

    for (int i = tid; i < 128 * 128; i += 256) {
        int r = i >> 7, c = i & 127;
        SWs[r * STRIDE + c] = tf32r(SWs[r * STRIDE + c]);
        As [r * STRIDE + c] = tf32r(As [r * STRIDE + c]);
    }

    {
        int r = tid >> 1, h = tid & 1;
        int n = n0 + r;
        int nc = (n > NNODES - 1) ? (NNODES - 1) : n;
        float s = 0.f;
        const float* row = sv + (size_t)nc * DDIM + h * 64;
        #pragma unroll
        for (int c = 0; c < 64; ++c) s += row[c] * gsw[h * 64 + c];
        s += __shfl_xor_sync(0xffffffffu, s, 1);
        if (h == 0 && n < NNODES) g_ts[n] = s;
    }
    __syncthreads();

    const int warp = tid >> 5, lane = tid & 31;
    const int wm = warp >> 1, wn = warp & 1;
    const int g = lane >> 2, tig = lane & 3;

    float acc[2][8][4];
    #pragma unroll
    for (int mf = 0; mf < 2; ++mf)
        #pragma unroll
        for (int nf = 0; nf < 8; ++nf)
            #pragma unroll
            for (int j = 0; j < 4; ++j) acc[mf][nf][j] = 0.f;

    #pragma unroll
    for (int ks = 0; ks < 16; ++ks) {
        const int kb = ks * 8;
        unsigned af[2][4];
        #pragma unroll
        for (int mf = 0; mf < 2; ++mf) {
            const float* ab = As + (wm * 32 + mf * 16) * STRIDE + kb;
            af[mf][0] = __float_as_uint(ab[g * STRIDE + tig]);
            af[mf][1] = __float_as_uint(ab[(g + 8) * STRIDE + tig]);
            af[mf][2] = __float_as_uint(ab[g * STRIDE + tig + 4]);
            af[mf][3] = __float_as_uint(ab[(g + 8) * STRIDE + tig + 4]);
        }
        #pragma unroll
        for (int nf = 0; nf < 8; ++nf) {
            const float* bb = SWs + kb * STRIDE + wn * 64 + nf * 8 + g;
            unsigned b0 = __float_as_uint(bb[tig * STRIDE]);
            unsigned b1 = __float_as_uint(bb[(tig + 4) * STRIDE]);
            #pragma unroll
            for (int mf = 0; mf < 2; ++mf) mma8(acc[mf][nf], af[mf], b0, b1);
        }
    }

    #pragma unroll
    for (int mf = 0; mf < 2; ++mf) {
        int lr = wm * 32 + mf * 16 + g;
        #pragma unroll
        for (int nf = 0; nf < 8; ++nf) {
            int col = wn * 64 + nf * 8 + tig * 2;
            int n1 = n0 + lr, n2 = n1 + 8;
            if (n1 < NNODES) {
                float2 v = make_float2(acc[mf][nf][0], acc[mf][nf][1]);
                *(float2*)&g_tsf[(size_t)n1 * DDIM + col] = v;
            }
            if (n2 < NNODES) {
                float2 v = make_float2(acc[mf][nf][2], acc[mf][nf][3]);
                *(float2*)&g_tsf[(size_t)n2 * DDIM + col] = v;
            }
        }
    }
}

// ---------------- main fused persistent kernel (TMA + swizzled tiles) ----------------
__global__ void __launch_bounds__(256, 1)
main_kernel(const __grid_constant__ CUtensorMap tml,   // link tensormap
            const __grid_constant__ CUtensorMap tmn,   // neigh tensormap
            const float* __restrict__ probs, const float* __restrict__ gnw_g,
            const float* __restrict__ glw_g, const float* __restrict__ lw,
            float* __restrict__ out)
{
    extern __shared__ __align__(1024) float sm[];
    float* Ws  = sm;
    float* gsm = sm + GSM_OFF;
    float* glw = sm + GLW_OFF;
    float* gnw = sm + GNW_OFF;
    unsigned long long* bars = (unsigned long long*)(sm + BAR_OFF);

    const int tid  = threadIdx.x;
    const int warp = tid >> 5, lane = tid & 31;
    const int wm = warp >> 2, wn = warp & 3;    // GEMM warp grid: 2 (nodes) x 4 (N cols)
    const int g = lane >> 2, tig = lane & 3;
    const int gstride = gridDim.x;

    // gate-phase thread mapping (conflict-free swizzled float4 reads)
    const int grr = lane & 7, gq = lane >> 3;
    const int gR  = warp * 8 + grr;             // row 0..63 handled by this thread

    // epilogue output column for this thread
    const int ecol = wn * 32 + (g >> 1) * 8 + tig * 2 + (g & 1);

    // one-time loads: W + gate weights via cp.async
    for (int i = tid; i < 128 * 32; i += 256) {
        int r = i >> 5, c4 = (i & 31) << 2;
        cp_async16(Ws + r * WSTRIDE + c4, lw + r * DDIM + c4);
    }
    if (tid < 32)      cp_async16(glw + tid * 4,        glw_g + tid * 4);
    else if (tid < 64) cp_async16(gnw + (tid - 32) * 4, gnw_g + (tid - 32) * 4);
    CP_COMMIT();

    if (tid == 0) { mbar_init(&bars[0], 1); mbar_init(&bars[1], 1); }
    __syncthreads();

    const int b0 = blockIdx.x;
    // issue first block into stage 0
    if (tid == 0 && b0 < NBLK) {
        mbar_expect(&bars[0], 2 * ROWS * DDIM * 4);
        #pragma unroll
        for (int bx = 0; bx < 4; ++bx) {
            tma2d(sm + TILE_OFF + bx * 2048,        &tml, bx * 32, b0 * ROWS, &bars[0]);
            tma2d(sm + TILE_OFF + 8192 + bx * 2048, &tmn, bx * 32, b0 * ROWS, &bars[0]);
        }
    }

    CP_WAIT(0);
    __syncthreads();
    for (int i = tid; i < 128 * 128; i += 256) {   // W -> tf32 once (in place)
        int r = i >> 7, c = i & 127;
        Ws[r * WSTRIDE + c] = tf32r(Ws[r * WSTRIDE + c]);
    }
    // visibility of W covered by the gate->GEMM __syncthreads below

    int ph[2] = {0, 0};
    int s = 0;
    for (int b = b0; b < NBLK; b += gstride) {
        const float* lks = sm + TILE_OFF + s * STAGE_SZ;
        const float* nbs = lks + 8192;

        // prefetch next block into the other stage
        int bn = b + gstride;
        if (tid == 0 && bn < NBLK) {
            float* lkn = sm + TILE_OFF + (s ^ 1) * STAGE_SZ;
            mbar_expect(&bars[s ^ 1], 2 * ROWS * DDIM * 4);
            #pragma unroll
            for (int bx = 0; bx < 4; ++bx) {
                tma2d(lkn + bx * 2048,        &tml, bx * 32, bn * ROWS, &bars[s ^ 1]);
                tma2d(lkn + 8192 + bx * 2048, &tmn, bx * 32, bn * ROWS, &bars[s ^ 1]);
            }
        }

        // early gmem prefetches (independent of tiles)
        const int node  = b * 2 + wm;
        float ts_pref = 0.f, pr_pref = 1.f;
        if (gq == 0) {
            ts_pref = g_ts[b * 2 + (gR >> 5)];
            pr_pref = probs[b * 64 + gR];
        }
        float tsf_pref = g_tsf[(size_t)node * DDIM + ecol];

        mbar_wait(&bars[s], ph[s]); ph[s] ^= 1;

        // ---- gate phase: conflict-free swizzled float4 dots ----
        {
            float tl = 0.f, tn = 0.f;
            #pragma unroll
            for (int j = 0; j < 8; ++j) {
                int c = gq * 32 + j * 4;
                float4 lv = *(const float4*)swz(lks, gR, c);
                float4 nv = *(const float4*)swz(nbs, gR, c);
                float4 gw = *(const float4*)&glw[c];
                float4 nw = *(const float4*)&gnw[c];
                tl += lv.x * gw.x + lv.y * gw.y + lv.z * gw.z + lv.w * gw.w;
                tn += nv.x * nw.x + nv.y * nw.y + nv.z * nw.z + nv.w * nw.w;
            }
            float t = tl + tn;
            t += __shfl_xor_sync(0xffffffffu, t, 8);
            t += __shfl_xor_sync(0xffffffffu, t, 16);
            if (gq == 0) gsm[gR] = sigm(ts_pref + t) / pr_pref;
        }
        __syncthreads();

        // ---- GEMM: L = tf32(link) @ W, warp tile 32x32 ----
        float acc[2][4][4];
        #pragma unroll
        for (int mf = 0; mf < 2; ++mf)
            #pragma unroll
            for (int nf = 0; nf < 4; ++nf)
                #pragma unroll
                for (int j = 0; j < 4; ++j) acc[mf][nf][j] = 0.f;

        #pragma unroll
        for (int ks = 0; ks < 16; ++ks) {
            const int kb = ks * 8;
            unsigned af[2][4];
            #pragma unroll
            for (int mf = 0; mf < 2; ++mf) {
                const int rb = wm * 32 + mf * 16;
                af[mf][0] = tf32u(*swz(lks, rb + g,     kb + tig));
                af[mf][1] = tf32u(*swz(lks, rb + g + 8, kb + tig));
                af[mf][2] = tf32u(*swz(lks, rb + g,     kb + tig + 4));
                af[mf][3] = tf32u(*swz(lks, rb + g + 8, kb + tig + 4));
            }
            #pragma unroll
            for (int nf = 0; nf < 4; ++nf) {
                const float* bb = Ws + kb * WSTRIDE + wn * 32 + nf * 8 + g;
                unsigned b0r = __float_as_uint(bb[tig * WSTRIDE]);
                unsigned b1r = __float_as_uint(bb[(tig + 4) * WSTRIDE]);
                mma8(acc[0][nf], af[0], b0r, b1r);
                mma8(acc[1][nf], af[1], b0r, b1r);
            }
        }

        // ---- epilogue: sigmoid, gate-weight, reduce over 32 neighbors ----
        float csum[4][2];
        #pragma unroll
        for (int nf = 0; nf < 4; ++nf) { csum[nf][0] = 0.f; csum[nf][1] = 0.f; }

        #pragma unroll
        for (int mf = 0; mf < 2; ++mf) {
            #pragma unroll
            for (int h = 0; h < 2; ++h) {
                int lr = wm * 32 + mf * 16 + h * 8 + g;
                float w = gsm[lr];
                #pragma unroll
                for (int nf = 0; nf < 4; ++nf) {
                    int col = wn * 32 + nf * 8 + tig * 2;
                    float2 nv = *(const float2*)swz(nbs, lr, col);
                    float s0 = sigm(acc[mf][nf][2 * h]);
                    float s1 = sigm(acc[mf][nf][2 * h + 1]);
                    csum[nf][0] += s0 * nv.x * w;
                    csum[nf][1] += s1 * nv.y * w;
                }
            }
        }
        #pragma unroll
        for (int off = 4; off <= 16; off <<= 1) {
            #pragma unroll
            for (int nf = 0; nf < 4; ++nf) {
                csum[nf][0] += __shfl_xor_sync(0xffffffffu, csum[nf][0], off);
                csum[nf][1] += __shfl_xor_sync(0xffffffffu, csum[nf][1], off);
            }
        }
        {
            int nf = g >> 1, j = g & 1;
            float v = csum[nf][j];
            float o = tsf_pref * v * (1.0f / 32.0f);
            out[(size_t)node * DDIM + ecol] = fmaxf(o, 0.f);
        }

        __syncthreads();   // all warps done with this stage before it is refilled
        s ^= 1;
    }
}

// ---------------- host: tensormap encode + launch ----------------
typedef CUresult (*EncFn)(CUtensorMap*, CUtensorMapDataType, cuuint32_t, void*,
                          const cuuint64_t*, const cuuint64_t*, const cuuint32_t*,
                          const cuuint32_t*, CUtensorMapInterleave, CUtensorMapSwizzle,
                          CUtensorMapL2promotion, CUtensorMapFloatOOBfill);

static EncFn get_encoder() {
    static EncFn fn = nullptr;
    if (!fn) {
        void* p = nullptr;
        cudaDriverEntryPointQueryResult st;
#if CUDART_VERSION >= 12050
        cudaGetDriverEntryPointByVersion("cuTensorMapEncodeTiled", &p, 12000,
                                         cudaEnableDefault, &st);
#else
        cudaGetDriverEntryPoint("cuTensorMapEncodeTiled", &p, cudaEnableDefault, &st);
#endif
        fn = (EncFn)p;
    }
    return fn;
}

static void make_map(CUtensorMap* m, const void* ptr) {
    cuuint64_t dims[2]    = {DDIM, (cuuint64_t)NNODES * KNEI};
    cuuint64_t strides[1] = {DDIM * 4};
    cuuint32_t box[2]     = {32, ROWS};
    cuuint32_t es[2]      = {1, 1};
    get_encoder()(m, CU_TENSOR_MAP_DATA_TYPE_FLOAT32, 2, (void*)ptr,
                  dims, strides, box, es,
                  CU_TENSOR_MAP_INTERLEAVE_NONE, CU_TENSOR_MAP_SWIZZLE_128B,
                  CU_TENSOR_MAP_L2_PROMOTION_L2_128B, CU_TENSOR_MAP_FLOAT_OOB_FILL_NONE);
}

extern "C" void kernel_launch(void* const* d_in, const int* in_sizes, int n_in,
                              void* d_out, int out_size)
{
    const float* self_feats   = (const float*)d_in[0];
    const float* self_vecs    = (const float*)d_in[1];
    const float* neigh_vecs   = (const float*)d_in[2];
    const float* link_vecs    = (const float*)d_in[3];
    const float* select_probs = (const float*)d_in[4];
    const float* gate_self_w  = (const float*)d_in[5];
    const float* gate_neigh_w = (const float*)d_in[6];
    const float* gate_link_w  = (const float*)d_in[7];
    const float* self_weights = (const float*)d_in[8];
    const float* link_weights = (const float*)d_in[9];
    float* out = (float*)d_out;

    CUtensorMap tml, tmn;
    make_map(&tml, link_vecs);
    make_map(&tmn, neigh_vecs);

    const int PRE_SMEM  = 33920 * 4;
    const int MAIN_SMEM = SMEM_FLOATS * 4;   // 202000 B
    cudaFuncSetAttribute(pre_kernel,  cudaFuncAttributeMaxDynamicSharedMemorySize, PRE_SMEM);
    cudaFuncSetAttribute(main_kernel, cudaFuncAttributeMaxDynamicSharedMemorySize, MAIN_SMEM);

    int sms = 148;
    cudaDeviceGetAttribute(&sms, cudaDevAttrMultiProcessorCount, 0);

    pre_kernel<<<(NNODES + 127) / 128, 256, PRE_SMEM>>>(
        self_feats, self_vecs, gate_self_w, self_weights);
    main_kernel<<<sms, 256, MAIN_SMEM>>>(
        tml, tmn, select_probs, gate_neigh_w, gate_link_w, link_weights, out);
}

// round 16
// speedup vs baseline: 1.5543x; 1.5543x over previous
#include <cuda_runtime.h>
#include <cuda.h>

#define NNODES 20000
#define DDIM   128
#define KNEI   32
#define ROWS   64            // rows per main block = 2 nodes * 32 neighbors
#define NBLK   (NNODES / 2)  // 10000 main blocks
#define STRIDE 132           // pre_kernel padded stride (unchanged)
#define WSTRIDE 136          // main kernel W stride: 136%32==8 -> conflict-free B frags

// ---- main-kernel smem layout (floats) ----
#define TILE_OFF 17408                     // after W (128*136)
#define STAGE_SZ 16384                     // link(8192) + neigh(8192) per stage
#define GSM_OFF  (TILE_OFF + 2*STAGE_SZ)   // 50176
#define GLW_OFF  (GSM_OFF + 64)            // 50240
#define GNW_OFF  (GLW_OFF + 128)           // 50368
#define BAR_OFF  (GNW_OFF + 128)           // 50496 (byte 201984, 8B aligned)
#define SMEM_FLOATS (BAR_OFF + 4)          // 50500 floats = 202000 bytes

// ---------------- scratch (device globals; no allocation) ----------------
__device__ float g_tsf[(size_t)NNODES * DDIM];  // self_feats @ self_weights
__device__ float g_ts[NNODES];                  // self_vecs . gate_self_w

// ---------------- helpers ----------------
__device__ __forceinline__ void cp_async16(float* smem_dst, const float* gmem_src) {
    unsigned s = (unsigned)__cvta_generic_to_shared(smem_dst);
    asm volatile("cp.async.cg.shared.global [%0], [%1], 16;\n" :: "r"(s), "l"(gmem_src));
}
#define CP_COMMIT() asm volatile("cp.async.commit_group;\n")
#define CP_WAIT(n)  asm volatile("cp.async.wait_group %0;\n" :: "n"(n))

__device__ __forceinline__ float tf32r(float x) {
    unsigned u;
    asm("cvt.rna.tf32.f32 %0, %1;" : "=r"(u) : "f"(x));
    return __uint_as_float(u);
}

__device__ __forceinline__ void mma8(float c[4], const unsigned a[4], unsigned b0, unsigned b1) {
    asm volatile(
        "mma.sync.aligned.m16n8k8.row.col.f32.tf32.tf32.f32 "
        "{%0,%1,%2,%3}, {%4,%5,%6,%7}, {%8,%9}, {%0,%1,%2,%3};\n"
        : "+f"(c[0]), "+f"(c[1]), "+f"(c[2]), "+f"(c[3])
        : "r"(a[0]), "r"(a[1]), "r"(a[2]), "r"(a[3]), "r"(b0), "r"(b1));
}

// precise sigmoid (pre_kernel + gate; 1 use per thread per iter)
__device__ __forceinline__ float sigm(float x) { return 1.f / (1.f + __expf(-x)); }

// fast sigmoid for the 32x epilogue: sigma(x) = 0.5*tanh(x/2)+0.5  (3 instr, 1 MUFU)
__device__ __forceinline__ float sigm_fast(float x) {
    float t;
    asm("tanh.approx.f32 %0, %1;" : "=f"(t) : "f"(x * 0.5f));
    return fmaf(t, 0.5f, 0.5f);
}

// swizzled SW128 tile accessor: tile = 4 boxes of [64 rows x 32 floats], 8KB each
__device__ __forceinline__ const float* swz(const float* base, int r, int c) {
    int off = ((c & 96) << 8)                                   // box * 8192 bytes
            + ((r * 128 + (c & 31) * 4) ^ ((r & 7) << 4));      // SW128 within box
    return (const float*)((const char*)base + off);
}
__device__ __forceinline__ float* swzm(float* base, int r, int c) {
    int off = ((c & 96) << 8)
            + ((r * 128 + (c & 31) * 4) ^ ((r & 7) << 4));
    return (float*)((char*)base + off);
}

// ---------------- mbarrier + TMA ----------------
__device__ __forceinline__ void mbar_init(void* bar, unsigned count) {
    unsigned a = (unsigned)__cvta_generic_to_shared(bar);
    asm volatile("mbarrier.init.shared.b64 [%0], %1;" :: "r"(a), "r"(count) : "memory");
}
__device__ __forceinline__ void mbar_expect(void* bar, unsigned bytes) {
    unsigned a = (unsigned)__cvta_generic_to_shared(bar);
    asm volatile("mbarrier.arrive.expect_tx.shared.b64 _, [%0], %1;" :: "r"(a), "r"(bytes) : "memory");
}
__device__ __forceinline__ void mbar_wait(void* bar, unsigned parity) {
    unsigned a = (unsigned)__cvta_generic_to_shared(bar);
    asm volatile(
        "{\n\t.reg .pred P%=;\n"
        "LW%=:\n\t"
        "mbarrier.try_wait.parity.acquire.cta.shared::cta.b64 P%=, [%0], %1, 0x989680;\n\t"
        "@P%= bra LD%=;\n\t"
        "bra LW%=;\n"
        "LD%=:\n\t}"
        :: "r"(a), "r"(parity) : "memory");
}
__device__ __forceinline__ void tma2d(void* smem_dst, const CUtensorMap* map,
                                      int x, int y, void* bar) {
    unsigned d = (unsigned)__cvta_generic_to_shared(smem_dst);
    unsigned b = (unsigned)__cvta_generic_to_shared(bar);
    asm volatile(
        "cp.async.bulk.tensor.2d.shared::cta.global.tile.mbarrier::complete_tx::bytes "
        "[%0], [%1, {%2, %3}], [%4];"
        :: "r"(d), "l"(map), "r"(x), "r"(y), "r"(b) : "memory");
}

// ---------------- precompute: g_tsf = sf @ SW  (tf32 mma), g_ts = sv . gsw ----------------
__global__ void __launch_bounds__(256, 1)
pre_kernel(const float* __restrict__ sf, const float* __restrict__ sv,
           const float* __restrict__ gsw_g, const float* __restrict__ sw)
{
    extern __shared__ float sm[];
    float* SWs = sm;
    float* As  = sm + 16896;
    float* gsw = sm + 33792;
    const int tid = threadIdx.x;
    const int n0  = blockIdx.x * 128;

    for (int i = tid; i < 128 * 32; i += 256) {
        int r = i >> 5, c4 = (i & 31) << 2;
        cp_async16(SWs + r * STRIDE + c4, sw + r * DDIM + c4);
    }
    for (int i = tid; i < 128 * 32; i += 256) {
        int r = i >> 5, c4 = (i & 31) << 2;
        int n = n0 + r; if (n > NNODES - 1) n = NNODES - 1;
        cp_async16(As + r * STRIDE + c4, sf + (size_t)n * DDIM + c4);
    }
    if (tid < 32) cp_async16(gsw + tid * 4, gsw_g + tid * 4);
    CP_COMMIT();
    CP_WAIT(0);
    __syncthreads();

    for (int i = tid; i < 128 * 128; i += 256) {
        int r = i >> 7, c = i & 127;
        SWs[r * STRIDE + c] = tf32r(SWs[r * STRIDE + c]);
        As [r * STRIDE + c] = tf32r(As [r * STRIDE + c]);
    }

    {
        int r = tid >> 1, h = tid & 1;
        int n = n0 + r;
        int nc = (n > NNODES - 1) ? (NNODES - 1) : n;
        float s = 0.f;
        const float* row = sv + (size_t)nc * DDIM + h * 64;
        #pragma unroll
        for (int c = 0; c < 64; ++c) s += row[c] * gsw[h * 64 + c];
        s += __shfl_xor_sync(0xffffffffu, s, 1);
        if (h == 0 && n < NNODES) g_ts[n] = s;
    }
    __syncthreads();

    const int warp = tid >> 5, lane = tid & 31;
    const int wm = warp >> 1, wn = warp & 1;
    const int g = lane >> 2, tig = lane & 3;

    float acc[2][8][4];
    #pragma unroll
    for (int mf = 0; mf < 2; ++mf)
        #pragma unroll
        for (int nf = 0; nf < 8; ++nf)
            #pragma unroll
            for (int j = 0; j < 4; ++j) acc[mf][nf][j] = 0.f;

    #pragma unroll
    for (int ks = 0; ks < 16; ++ks) {
        const int kb = ks * 8;
        unsigned af[2][4];
        #pragma unroll
        for (int mf = 0; mf < 2; ++mf) {
            const float* ab = As + (wm * 32 + mf * 16) * STRIDE + kb;
            af[mf][0] = __float_as_uint(ab[g * STRIDE + tig]);
            af[mf][1] = __float_as_uint(ab[(g + 8) * STRIDE + tig]);
            af[mf][2] = __float_as_uint(ab[g * STRIDE + tig + 4]);
            af[mf][3] = __float_as_uint(ab[(g + 8) * STRIDE + tig + 4]);
        }
        #pragma unroll
        for (int nf = 0; nf < 8; ++nf) {
            const float* bb = SWs + kb * STRIDE + wn * 64 + nf * 8 + g;
            unsigned b0 = __float_as_uint(bb[tig * STRIDE]);
            unsigned b1 = __float_as_uint(bb[(tig + 4) * STRIDE]);
            #pragma unroll
            for (int mf = 0; mf < 2; ++mf) mma8(acc[mf][nf], af[mf], b0, b1);
        }
    }

    #pragma unroll
    for (int mf = 0; mf < 2; ++mf) {
        int lr = wm * 32 + mf * 16 + g;
        #pragma unroll
        for (int nf = 0; nf < 8; ++nf) {
            int col = wn * 64 + nf * 8 + tig * 2;
            int n1 = n0 + lr, n2 = n1 + 8;
            if (n1 < NNODES) {
                float2 v = make_float2(acc[mf][nf][0], acc[mf][nf][1]);
                *(float2*)&g_tsf[(size_t)n1 * DDIM + col] = v;
            }
            if (n2 < NNODES) {
                float2 v = make_float2(acc[mf][nf][2], acc[mf][nf][3]);
                *(float2*)&g_tsf[(size_t)n2 * DDIM + col] = v;
            }
        }
    }
}

// ---------------- main fused persistent kernel (TMA + swizzled tiles) ----------------
__global__ void __launch_bounds__(256, 1)
main_kernel(const __grid_constant__ CUtensorMap tml,   // link tensormap
            const __grid_constant__ CUtensorMap tmn,   // neigh tensormap
            const float* __restrict__ probs, const float* __restrict__ gnw_g,
            const float* __restrict__ glw_g, const float* __restrict__ lw,
            float* __restrict__ out)
{
    extern __shared__ __align__(1024) float sm[];
    float* Ws  = sm;
    float* gsm = sm + GSM_OFF;
    float* glw = sm + GLW_OFF;
    float* gnw = sm + GNW_OFF;
    unsigned long long* bars = (unsigned long long*)(sm + BAR_OFF);

    const int tid  = threadIdx.x;
    const int warp = tid >> 5, lane = tid & 31;
    const int wm = warp >> 2, wn = warp & 3;    // GEMM warp grid: 2 (nodes) x 4 (N cols)
    const int g = lane >> 2, tig = lane & 3;
    const int gstride = gridDim.x;

    // gate-phase thread mapping (conflict-free swizzled float4 reads)
    const int grr = lane & 7, gq = lane >> 3;
    const int gR  = warp * 8 + grr;             // row 0..63 handled by this thread

    // epilogue output column for this thread
    const int ecol = wn * 32 + (g >> 1) * 8 + tig * 2 + (g & 1);

    // one-time loads: W + gate weights via cp.async
    for (int i = tid; i < 128 * 32; i += 256) {
        int r = i >> 5, c4 = (i & 31) << 2;
        cp_async16(Ws + r * WSTRIDE + c4, lw + r * DDIM + c4);
    }
    if (tid < 32)      cp_async16(glw + tid * 4,        glw_g + tid * 4);
    else if (tid < 64) cp_async16(gnw + (tid - 32) * 4, gnw_g + (tid - 32) * 4);
    CP_COMMIT();

    if (tid == 0) { mbar_init(&bars[0], 1); mbar_init(&bars[1], 1); }
    __syncthreads();

    const int b0 = blockIdx.x;
    // issue first block into stage 0
    if (tid == 0 && b0 < NBLK) {
        mbar_expect(&bars[0], 2 * ROWS * DDIM * 4);
        #pragma unroll
        for (int bx = 0; bx < 4; ++bx) {
            tma2d(sm + TILE_OFF + bx * 2048,        &tml, bx * 32, b0 * ROWS, &bars[0]);
            tma2d(sm + TILE_OFF + 8192 + bx * 2048, &tmn, bx * 32, b0 * ROWS, &bars[0]);
        }
    }

    CP_WAIT(0);
    __syncthreads();
    for (int i = tid; i < 128 * 128; i += 256) {   // W -> tf32 once (in place)
        int r = i >> 7, c = i & 127;
        Ws[r * WSTRIDE + c] = tf32r(Ws[r * WSTRIDE + c]);
    }
    __syncthreads();                               // W visible for B reg-cache

    // ---- register-cache the k<64 half of this thread's B fragments ----
    unsigned bc[8][4][2];
    #pragma unroll
    for (int ks = 0; ks < 8; ++ks) {
        #pragma unroll
        for (int nf = 0; nf < 4; ++nf) {
            const float* bb = Ws + (ks * 8) * WSTRIDE + wn * 32 + nf * 8 + g;
            bc[ks][nf][0] = __float_as_uint(bb[tig * WSTRIDE]);
            bc[ks][nf][1] = __float_as_uint(bb[(tig + 4) * WSTRIDE]);
        }
    }

    int ph[2] = {0, 0};
    int s = 0;
    for (int b = b0; b < NBLK; b += gstride) {
        float* lks_m = sm + TILE_OFF + s * STAGE_SZ;   // mutable: gate converts in place
        const float* lks = lks_m;
        const float* nbs = lks + 8192;

        // prefetch next block into the other stage
        int bn = b + gstride;
        if (tid == 0 && bn < NBLK) {
            float* lkn = sm + TILE_OFF + (s ^ 1) * STAGE_SZ;
            mbar_expect(&bars[s ^ 1], 2 * ROWS * DDIM * 4);
            #pragma unroll
            for (int bx = 0; bx < 4; ++bx) {
                tma2d(lkn + bx * 2048,        &tml, bx * 32, bn * ROWS, &bars[s ^ 1]);
                tma2d(lkn + 8192 + bx * 2048, &tmn, bx * 32, bn * ROWS, &bars[s ^ 1]);
            }
        }

        // early gmem prefetches (independent of tiles)
        const int node  = b * 2 + wm;
        float ts_pref = 0.f, pr_pref = 1.f;
        if (gq == 0) {
            ts_pref = g_ts[b * 2 + (gR >> 5)];
            pr_pref = probs[b * 64 + gR];
        }
        float tsf_pref = g_tsf[(size_t)node * DDIM + ecol];

        mbar_wait(&bars[s], ph[s]); ph[s] ^= 1;

        // ---- gate phase: swizzled float4 dots + in-place tf32 convert of link ----
        {
            float tl = 0.f, tn = 0.f;
            #pragma unroll
            for (int j = 0; j < 8; ++j) {
                int c = gq * 32 + j * 4;
                float4 lv = *(const float4*)swz(lks, gR, c);
                float4 nv = *(const float4*)swz(nbs, gR, c);
                float4 gw = *(const float4*)&glw[c];
                float4 nw = *(const float4*)&gnw[c];
                tl += lv.x * gw.x + lv.y * gw.y + lv.z * gw.z + lv.w * gw.w;
                tn += nv.x * nw.x + nv.y * nw.y + nv.z * nw.z + nv.w * nw.w;
                float4 cv;                          // tf32 write-back (each element
                cv.x = tf32r(lv.x); cv.y = tf32r(lv.y);   // owned by exactly one thread)
                cv.z = tf32r(lv.z); cv.w = tf32r(lv.w);
                *(float4*)swzm(lks_m, gR, c) = cv;
            }
            float t = tl + tn;
            t += __shfl_xor_sync(0xffffffffu, t, 8);
            t += __shfl_xor_sync(0xffffffffu, t, 16);
            if (gq == 0)
                gsm[gR] = __fdividef(1.f, (1.f + __expf(-(ts_pref + t))) * pr_pref);
        }
        __syncthreads();

        // ---- GEMM: L = tf32(link) @ W, warp tile 32x32 ----
        float acc[2][4][4];
        #pragma unroll
        for (int mf = 0; mf < 2; ++mf)
            #pragma unroll
            for (int nf = 0; nf < 4; ++nf)
                #pragma unroll
                for (int j = 0; j < 4; ++j) acc[mf][nf][j] = 0.f;

        #pragma unroll
        for (int ks = 0; ks < 16; ++ks) {
            const int kb = ks * 8;
            unsigned af[2][4];
            #pragma unroll
            for (int mf = 0; mf < 2; ++mf) {
                const int rb = wm * 32 + mf * 16;
                af[mf][0] = __float_as_uint(*swz(lks, rb + g,     kb + tig));
                af[mf][1] = __float_as_uint(*swz(lks, rb + g + 8, kb + tig));
                af[mf][2] = __float_as_uint(*swz(lks, rb + g,     kb + tig + 4));
                af[mf][3] = __float_as_uint(*swz(lks, rb + g + 8, kb + tig + 4));
            }
            #pragma unroll
            for (int nf = 0; nf < 4; ++nf) {
                unsigned b0r, b1r;
                if (ks < 8) {                       // resolved at compile time
                    b0r = bc[ks][nf][0];
                    b1r = bc[ks][nf][1];
                } else {
                    const float* bb = Ws + kb * WSTRIDE + wn * 32 + nf * 8 + g;
                    b0r = __float_as_uint(bb[tig * WSTRIDE]);
                    b1r = __float_as_uint(bb[(tig + 4) * WSTRIDE]);
                }
                mma8(acc[0][nf], af[0], b0r, b1r);
                mma8(acc[1][nf], af[1], b0r, b1r);
            }
        }

        // ---- epilogue: fast sigmoid, gate-weight, reduce over 32 neighbors ----
        float csum[4][2];
        #pragma unroll
        for (int nf = 0; nf < 4; ++nf) { csum[nf][0] = 0.f; csum[nf][1] = 0.f; }

        #pragma unroll
        for (int mf = 0; mf < 2; ++mf) {
            #pragma unroll
            for (int h = 0; h < 2; ++h) {
                int lr = wm * 32 + mf * 16 + h * 8 + g;
                float w = gsm[lr];
                #pragma unroll
                for (int nf = 0; nf < 4; ++nf) {
                    int col = wn * 32 + nf * 8 + tig * 2;
                    float2 nv = *(const float2*)swz(nbs, lr, col);
                    float s0 = sigm_fast(acc[mf][nf][2 * h]);
                    float s1 = sigm_fast(acc[mf][nf][2 * h + 1]);
                    csum[nf][0] += s0 * nv.x * w;
                    csum[nf][1] += s1 * nv.y * w;
                }
            }
        }
        #pragma unroll
        for (int off = 4; off <= 16; off <<= 1) {
            #pragma unroll
            for (int nf = 0; nf < 4; ++nf) {
                csum[nf][0] += __shfl_xor_sync(0xffffffffu, csum[nf][0], off);
                csum[nf][1] += __shfl_xor_sync(0xffffffffu, csum[nf][1], off);
            }
        }
        {
            int nf = g >> 1, j = g & 1;
            float v = csum[nf][j];
            float o = tsf_pref * v * (1.0f / 32.0f);
            out[(size_t)node * DDIM + ecol] = fmaxf(o, 0.f);
        }

        __syncthreads();   // all warps done with this stage before it is refilled
        s ^= 1;
    }
}

// ---------------- host: tensormap encode + launch ----------------
typedef CUresult (*EncFn)(CUtensorMap*, CUtensorMapDataType, cuuint32_t, void*,
                          const cuuint64_t*, const cuuint64_t*, const cuuint32_t*,
                          const cuuint32_t*, CUtensorMapInterleave, CUtensorMapSwizzle,
                          CUtensorMapL2promotion, CUtensorMapFloatOOBfill);

static EncFn get_encoder() {
    static EncFn fn = nullptr;
    if (!fn) {
        void* p = nullptr;
        cudaDriverEntryPointQueryResult st;
#if CUDART_VERSION >= 12050
        cudaGetDriverEntryPointByVersion("cuTensorMapEncodeTiled", &p, 12000,
                                         cudaEnableDefault, &st);
#else
        cudaGetDriverEntryPoint("cuTensorMapEncodeTiled", &p, cudaEnableDefault, &st);
#endif
        fn = (EncFn)p;
    }
    return fn;
}

static void make_map(CUtensorMap* m, const void* ptr) {
    cuuint64_t dims[2]    = {DDIM, (cuuint64_t)NNODES * KNEI};
    cuuint64_t strides[1] = {DDIM * 4};
    cuuint32_t box[2]     = {32, ROWS};
    cuuint32_t es[2]      = {1, 1};
    get_encoder()(m, CU_TENSOR_MAP_DATA_TYPE_FLOAT32, 2, (void*)ptr,
                  dims, strides, box, es,
                  CU_TENSOR_MAP_INTERLEAVE_NONE, CU_TENSOR_MAP_SWIZZLE_128B,
                  CU_TENSOR_MAP_L2_PROMOTION_L2_128B, CU_TENSOR_MAP_FLOAT_OOB_FILL_NONE);
}

extern "C" void kernel_launch(void* const* d_in, const int* in_sizes, int n_in,
                              void* d_out, int out_size)
{
    const float* self_feats   = (const float*)d_in[0];
    const float* self_vecs    = (const float*)d_in[1];
    const float* neigh_vecs   = (const float*)d_in[2];
    const float* link_vecs    = (const float*)d_in[3];
    const float* select_probs = (const float*)d_in[4];
    const float* gate_self_w  = (const float*)d_in[5];
    const float* gate_neigh_w = (const float*)d_in[6];
    const float* gate_link_w  = (const float*)d_in[7];
    const float* self_weights = (const float*)d_in[8];
    const float* link_weights = (const float*)d_in[9];
    float* out = (float*)d_out;

    CUtensorMap tml, tmn;
    make_map(&tml, link_vecs);
    make_map(&tmn, neigh_vecs);

    const int PRE_SMEM  = 33920 * 4;
    const int MAIN_SMEM = SMEM_FLOATS * 4;   // 202000 B
    cudaFuncSetAttribute(pre_kernel,  cudaFuncAttributeMaxDynamicSharedMemorySize, PRE_SMEM);
    cudaFuncSetAttribute(main_kernel, cudaFuncAttributeMaxDynamicSharedMemorySize, MAIN_SMEM);

    int sms = 148;
    cudaDeviceGetAttribute(&sms, cudaDevAttrMultiProcessorCount, 0);

    pre_kernel<<<(NNODES + 127) / 128, 256, PRE_SMEM>>>(
        self_feats, self_vecs, gate_self_w, self_weights);
    main_kernel<<<sms, 256, MAIN_SMEM>>>(
        tml, tmn, select_probs, gate_neigh_w, gate_link_w, link_weights, out);
}

// round 17
// speedup vs baseline: 1.5636x; 1.0060x over previous
#include <cuda_runtime.h>
#include <cuda.h>

#define NNODES 20000
#define DDIM   128
#define KNEI   32
#define ROWS   64            // rows per main block = 2 nodes * 32 neighbors
#define NBLK   (NNODES / 2)  // 10000 main blocks
#define STRIDE 132           // pre_kernel padded stride
#define WSTRIDE 136          // main kernel W stride: 136%32==8 -> conflict-free B frags

// ---- pre-kernel smem (floats): SWs[0,16896) | As[16896,25344) | gsw[25344,25472)
#define PRE_CHUNK 64
#define PRE_AS_OFF 16896
#define PRE_GSW_OFF 25344
#define PRE_FLOATS 25472                   // 101888 bytes -> 2 CTAs/SM

// ---- main-kernel smem layout (floats) ----
#define TILE_OFF 17408                     // after W (128*136)
#define STAGE_SZ 16384                     // link(8192) + neigh(8192) per stage
#define GSM_OFF  (TILE_OFF + 2*STAGE_SZ)   // 50176
#define GLW_OFF  (GSM_OFF + 64)            // 50240
#define GNW_OFF  (GLW_OFF + 128)           // 50368
#define BAR_OFF  (GNW_OFF + 128)           // 50496 (byte 201984, 8B aligned)
#define SMEM_FLOATS (BAR_OFF + 4)          // 50500 floats = 202000 bytes

// ---------------- scratch (device globals; no allocation) ----------------
__device__ float g_tsf[(size_t)NNODES * DDIM];  // self_feats @ self_weights
__device__ float g_ts[NNODES];                  // self_vecs . gate_self_w

// ---------------- helpers ----------------
__device__ __forceinline__ void cp_async16(float* smem_dst, const float* gmem_src) {
    unsigned s = (unsigned)__cvta_generic_to_shared(smem_dst);
    asm volatile("cp.async.cg.shared.global [%0], [%1], 16;\n" :: "r"(s), "l"(gmem_src));
}
#define CP_COMMIT() asm volatile("cp.async.commit_group;\n")
#define CP_WAIT(n)  asm volatile("cp.async.wait_group %0;\n" :: "n"(n))

__device__ __forceinline__ float tf32r(float x) {
    unsigned u;
    asm("cvt.rna.tf32.f32 %0, %1;" : "=r"(u) : "f"(x));
    return __uint_as_float(u);
}

__device__ __forceinline__ void mma8(float c[4], const unsigned a[4], unsigned b0, unsigned b1) {
    asm volatile(
        "mma.sync.aligned.m16n8k8.row.col.f32.tf32.tf32.f32 "
        "{%0,%1,%2,%3}, {%4,%5,%6,%7}, {%8,%9}, {%0,%1,%2,%3};\n"
        : "+f"(c[0]), "+f"(c[1]), "+f"(c[2]), "+f"(c[3])
        : "r"(a[0]), "r"(a[1]), "r"(a[2]), "r"(a[3]), "r"(b0), "r"(b1));
}

// ldmatrix x4: loads 4 8x(4 float) tiles; fragment layout == tf32 A-frag layout
__device__ __forceinline__ void ldm_x4(unsigned r[4], const void* p) {
    unsigned a = (unsigned)__cvta_generic_to_shared(p);
    asm volatile("ldmatrix.sync.aligned.m8n8.x4.shared.b16 {%0,%1,%2,%3}, [%4];"
                 : "=r"(r[0]), "=r"(r[1]), "=r"(r[2]), "=r"(r[3]) : "r"(a));
}

// precise sigmoid (pre + gate; 1 use per thread per iter)
__device__ __forceinline__ float sigm(float x) { return 1.f / (1.f + __expf(-x)); }

// fast sigmoid for the 32x epilogue
__device__ __forceinline__ float sigm_fast(float x) {
    float t;
    asm("tanh.approx.f32 %0, %1;" : "=f"(t) : "f"(x * 0.5f));
    return fmaf(t, 0.5f, 0.5f);
}

// swizzled SW128 tile accessor: tile = 4 boxes of [64 rows x 32 floats], 8KB each
__device__ __forceinline__ const float* swz(const float* base, int r, int c) {
    int off = ((c & 96) << 8)
            + ((r * 128 + (c & 31) * 4) ^ ((r & 7) << 4));
    return (const float*)((const char*)base + off);
}
__device__ __forceinline__ float* swzm(float* base, int r, int c) {
    int off = ((c & 96) << 8)
            + ((r * 128 + (c & 31) * 4) ^ ((r & 7) << 4));
    return (float*)((char*)base + off);
}

// ---------------- mbarrier + TMA ----------------
__device__ __forceinline__ void mbar_init(void* bar, unsigned count) {
    unsigned a = (unsigned)__cvta_generic_to_shared(bar);
    asm volatile("mbarrier.init.shared.b64 [%0], %1;" :: "r"(a), "r"(count) : "memory");
}
__device__ __forceinline__ void mbar_expect(void* bar, unsigned bytes) {
    unsigned a = (unsigned)__cvta_generic_to_shared(bar);
    asm volatile("mbarrier.arrive.expect_tx.shared.b64 _, [%0], %1;" :: "r"(a), "r"(bytes) : "memory");
}
__device__ __forceinline__ void mbar_wait(void* bar, unsigned parity) {
    unsigned a = (unsigned)__cvta_generic_to_shared(bar);
    asm volatile(
        "{\n\t.reg .pred P%=;\n"
        "LW%=:\n\t"
        "mbarrier.try_wait.parity.acquire.cta.shared::cta.b64 P%=, [%0], %1, 0x989680;\n\t"
        "@P%= bra LD%=;\n\t"
        "bra LW%=;\n"
        "LD%=:\n\t}"
        :: "r"(a), "r"(parity) : "memory");
}
__device__ __forceinline__ void tma2d(void* smem_dst, const CUtensorMap* map,
                                      int x, int y, void* bar) {
    unsigned d = (unsigned)__cvta_generic_to_shared(smem_dst);
    unsigned b = (unsigned)__cvta_generic_to_shared(bar);
    asm volatile(
        "cp.async.bulk.tensor.2d.shared::cta.global.tile.mbarrier::complete_tx::bytes "
        "[%0], [%1, {%2, %3}], [%4];"
        :: "r"(d), "l"(map), "r"(x), "r"(y), "r"(b) : "memory");
}

// ---------------- precompute: 64-node chunks, 2 CTAs/SM ----------------
__global__ void __launch_bounds__(256, 2)
pre_kernel(const float* __restrict__ sf, const float* __restrict__ sv,
           const float* __restrict__ gsw_g, const float* __restrict__ sw)
{
    extern __shared__ float sm[];
    float* SWs = sm;
    float* As  = sm + PRE_AS_OFF;
    float* gsw = sm + PRE_GSW_OFF;
    const int tid = threadIdx.x;
    const int n0  = blockIdx.x * PRE_CHUNK;

    for (int i = tid; i < 128 * 32; i += 256) {
        int r = i >> 5, c4 = (i & 31) << 2;
        cp_async16(SWs + r * STRIDE + c4, sw + r * DDIM + c4);
    }
    for (int i = tid; i < PRE_CHUNK * 32; i += 256) {
        int r = i >> 5, c4 = (i & 31) << 2;
        int n = n0 + r; if (n > NNODES - 1) n = NNODES - 1;
        cp_async16(As + r * STRIDE + c4, sf + (size_t)n * DDIM + c4);
    }
    if (tid < 32) cp_async16(gsw + tid * 4, gsw_g + tid * 4);
    CP_COMMIT();
    CP_WAIT(0);
    __syncthreads();

    // tf32 convert both tiles
    for (int i = tid; i < 128 * 128; i += 256) {
        int r = i >> 7, c = i & 127;
        SWs[r * STRIDE + c] = tf32r(SWs[r * STRIDE + c]);
    }
    for (int i = tid; i < PRE_CHUNK * 128; i += 256) {
        int r = i >> 7, c = i & 127;
        As[r * STRIDE + c] = tf32r(As[r * STRIDE + c]);
    }

    // g_ts: 4 threads per row
    {
        int r = tid >> 2, h = tid & 3;
        int n = n0 + r;
        int nc = (n > NNODES - 1) ? (NNODES - 1) : n;
        float s = 0.f;
        const float* row = sv + (size_t)nc * DDIM + h * 32;
        #pragma unroll
        for (int c = 0; c < 32; ++c) s += row[c] * gsw[h * 32 + c];
        s += __shfl_xor_sync(0xffffffffu, s, 1);
        s += __shfl_xor_sync(0xffffffffu, s, 2);
        if (h == 0 && n < NNODES) g_ts[n] = s;
    }
    __syncthreads();

    // GEMM: 64 x 128 = As @ SWs, warp grid 2 (rows) x 4 (cols), tile 32x32
    const int warp = tid >> 5, lane = tid & 31;
    const int wm = warp >> 2, wn = warp & 3;
    const int g = lane >> 2, tig = lane & 3;

    float acc[2][4][4];
    #pragma unroll
    for (int mf = 0; mf < 2; ++mf)
        #pragma unroll
        for (int nf = 0; nf < 4; ++nf)
            #pragma unroll
            for (int j = 0; j < 4; ++j) acc[mf][nf][j] = 0.f;

    #pragma unroll
    for (int ks = 0; ks < 16; ++ks) {
        const int kb = ks * 8;
        unsigned af[2][4];
        #pragma unroll
        for (int mf = 0; mf < 2; ++mf) {
            const float* ab = As + (wm * 32 + mf * 16) * STRIDE + kb;
            af[mf][0] = __float_as_uint(ab[g * STRIDE + tig]);
            af[mf][1] = __float_as_uint(ab[(g + 8) * STRIDE + tig]);
            af[mf][2] = __float_as_uint(ab[g * STRIDE + tig + 4]);
            af[mf][3] = __float_as_uint(ab[(g + 8) * STRIDE + tig + 4]);
        }
        #pragma unroll
        for (int nf = 0; nf < 4; ++nf) {
            const float* bb = SWs + kb * STRIDE + wn * 32 + nf * 8 + g;
            unsigned b0 = __float_as_uint(bb[tig * STRIDE]);
            unsigned b1 = __float_as_uint(bb[(tig + 4) * STRIDE]);
            #pragma unroll
            for (int mf = 0; mf < 2; ++mf) mma8(acc[mf][nf], af[mf], b0, b1);
        }
    }

    #pragma unroll
    for (int mf = 0; mf < 2; ++mf) {
        int lr = wm * 32 + mf * 16 + g;
        #pragma unroll
        for (int nf = 0; nf < 4; ++nf) {
            int col = wn * 32 + nf * 8 + tig * 2;
            int n1 = n0 + lr, n2 = n1 + 8;
            if (n1 < NNODES)
                *(float2*)&g_tsf[(size_t)n1 * DDIM + col] = make_float2(acc[mf][nf][0], acc[mf][nf][1]);
            if (n2 < NNODES)
                *(float2*)&g_tsf[(size_t)n2 * DDIM + col] = make_float2(acc[mf][nf][2], acc[mf][nf][3]);
        }
    }
}

// ---------------- main fused persistent kernel (TMA + swizzled tiles) ----------------
__global__ void __launch_bounds__(256, 1)
main_kernel(const __grid_constant__ CUtensorMap tml,   // link tensormap
            const __grid_constant__ CUtensorMap tmn,   // neigh tensormap
            const float* __restrict__ probs, const float* __restrict__ gnw_g,
            const float* __restrict__ glw_g, const float* __restrict__ lw,
            float* __restrict__ out)
{
    extern __shared__ __align__(1024) float sm[];
    float* Ws  = sm;
    float* gsm = sm + GSM_OFF;
    float* glw = sm + GLW_OFF;
    float* gnw = sm + GNW_OFF;
    unsigned long long* bars = (unsigned long long*)(sm + BAR_OFF);

    const int tid  = threadIdx.x;
    const int warp = tid >> 5, lane = tid & 31;
    const int wm = warp >> 2, wn = warp & 3;    // GEMM warp grid: 2 (nodes) x 4 (N cols)
    const int g = lane >> 2, tig = lane & 3;
    const int gstride = gridDim.x;

    // ldmatrix per-lane source row/col within the warp's 32-row A tile
    const int lrow = (lane & 7) + (((lane >> 3) & 1) << 3);   // 0..15
    const int lcb  = (lane >> 4) << 2;                        // 0 or 4

    // gate-phase thread mapping (conflict-free swizzled float4 reads)
    const int grr = lane & 7, gq = lane >> 3;
    const int gR  = warp * 8 + grr;             // row 0..63 handled by this thread

    // epilogue output column for this thread
    const int ecol = wn * 32 + (g >> 1) * 8 + tig * 2 + (g & 1);

    // one-time loads: W + gate weights via cp.async
    for (int i = tid; i < 128 * 32; i += 256) {
        int r = i >> 5, c4 = (i & 31) << 2;
        cp_async16(Ws + r * WSTRIDE + c4, lw + r * DDIM + c4);
    }
    if (tid < 32)      cp_async16(glw + tid * 4,        glw_g + tid * 4);
    else if (tid < 64) cp_async16(gnw + (tid - 32) * 4, gnw_g + (tid - 32) * 4);
    CP_COMMIT();

    if (tid == 0) { mbar_init(&bars[0], 1); mbar_init(&bars[1], 1); }
    __syncthreads();

    const int b0 = blockIdx.x;
    if (tid == 0 && b0 < NBLK) {
        mbar_expect(&bars[0], 2 * ROWS * DDIM * 4);
        #pragma unroll
        for (int bx = 0; bx < 4; ++bx) {
            tma2d(sm + TILE_OFF + bx * 2048,        &tml, bx * 32, b0 * ROWS, &bars[0]);
            tma2d(sm + TILE_OFF + 8192 + bx * 2048, &tmn, bx * 32, b0 * ROWS, &bars[0]);
        }
    }

    CP_WAIT(0);
    __syncthreads();
    for (int i = tid; i < 128 * 128; i += 256) {   // W -> tf32 once (in place)
        int r = i >> 7, c = i & 127;
        Ws[r * WSTRIDE + c] = tf32r(Ws[r * WSTRIDE + c]);
    }
    __syncthreads();                               // W visible for B reg-cache

    // ---- register-cache the k<64 half of this thread's B fragments ----
    unsigned bc[8][4][2];
    #pragma unroll
    for (int ks = 0; ks < 8; ++ks) {
        #pragma unroll
        for (int nf = 0; nf < 4; ++nf) {
            const float* bb = Ws + (ks * 8) * WSTRIDE + wn * 32 + nf * 8 + g;
            bc[ks][nf][0] = __float_as_uint(bb[tig * WSTRIDE]);
            bc[ks][nf][1] = __float_as_uint(bb[(tig + 4) * WSTRIDE]);
        }
    }

    int ph[2] = {0, 0};
    int s = 0;
    for (int b = b0; b < NBLK; b += gstride) {
        float* lks_m = sm + TILE_OFF + s * STAGE_SZ;   // mutable: gate converts in place
        const float* lks = lks_m;
        const float* nbs = lks + 8192;

        // prefetch next block into the other stage
        int bn = b + gstride;
        if (tid == 0 && bn < NBLK) {
            float* lkn = sm + TILE_OFF + (s ^ 1) * STAGE_SZ;
            mbar_expect(&bars[s ^ 1], 2 * ROWS * DDIM * 4);
            #pragma unroll
            for (int bx = 0; bx < 4; ++bx) {
                tma2d(lkn + bx * 2048,        &tml, bx * 32, bn * ROWS, &bars[s ^ 1]);
                tma2d(lkn + 8192 + bx * 2048, &tmn, bx * 32, bn * ROWS, &bars[s ^ 1]);
            }
        }

        // early gmem prefetches (independent of tiles)
        const int node  = b * 2 + wm;
        float ts_pref = 0.f, pr_pref = 1.f;
        if (gq == 0) {
            ts_pref = g_ts[b * 2 + (gR >> 5)];
            pr_pref = probs[b * 64 + gR];
        }
        float tsf_pref = g_tsf[(size_t)node * DDIM + ecol];

        mbar_wait(&bars[s], ph[s]); ph[s] ^= 1;

        // ---- gate phase: swizzled float4 dots + in-place tf32 convert of link ----
        {
            float tl = 0.f, tn = 0.f;
            #pragma unroll
            for (int j = 0; j < 8; ++j) {
                int c = gq * 32 + j * 4;
                float4 lv = *(const float4*)swz(lks, gR, c);
                float4 nv = *(const float4*)swz(nbs, gR, c);
                float4 gw = *(const float4*)&glw[c];
                float4 nw = *(const float4*)&gnw[c];
                tl += lv.x * gw.x + lv.y * gw.y + lv.z * gw.z + lv.w * gw.w;
                tn += nv.x * nw.x + nv.y * nw.y + nv.z * nw.z + nv.w * nw.w;
                float4 cv;
                cv.x = tf32r(lv.x); cv.y = tf32r(lv.y);
                cv.z = tf32r(lv.z); cv.w = tf32r(lv.w);
                *(float4*)swzm(lks_m, gR, c) = cv;
            }
            float t = tl + tn;
            t += __shfl_xor_sync(0xffffffffu, t, 8);
            t += __shfl_xor_sync(0xffffffffu, t, 16);
            if (gq == 0)
                gsm[gR] = __fdividef(1.f, (1.f + __expf(-(ts_pref + t))) * pr_pref);
        }
        __syncthreads();

        // ---- GEMM: L = tf32(link) @ W, warp tile 32x32, A via ldmatrix ----
        float acc[2][4][4];
        #pragma unroll
        for (int mf = 0; mf < 2; ++mf)
            #pragma unroll
            for (int nf = 0; nf < 4; ++nf)
                #pragma unroll
                for (int j = 0; j < 4; ++j) acc[mf][nf][j] = 0.f;

        #pragma unroll
        for (int ks = 0; ks < 16; ++ks) {
            const int kb = ks * 8;
            unsigned af[2][4];
            ldm_x4(af[0], swz(lks, wm * 32 +      lrow, kb + lcb));
            ldm_x4(af[1], swz(lks, wm * 32 + 16 + lrow, kb + lcb));
            #pragma unroll
            for (int nf = 0; nf < 4; ++nf) {
                unsigned b0r, b1r;
                if (ks < 8) {
                    b0r = bc[ks][nf][0];
                    b1r = bc[ks][nf][1];
                } else {
                    const float* bb = Ws + kb * WSTRIDE + wn * 32 + nf * 8 + g;
                    b0r = __float_as_uint(bb[tig * WSTRIDE]);
                    b1r = __float_as_uint(bb[(tig + 4) * WSTRIDE]);
                }
                mma8(acc[0][nf], af[0], b0r, b1r);
                mma8(acc[1][nf], af[1], b0r, b1r);
            }
        }

        // ---- epilogue: fast sigmoid, gate-weight, reduce over 32 neighbors ----
        float csum[4][2];
        #pragma unroll
        for (int nf = 0; nf < 4; ++nf) { csum[nf][0] = 0.f; csum[nf][1] = 0.f; }

        #pragma unroll
        for (int mf = 0; mf < 2; ++mf) {
            #pragma unroll
            for (int h = 0; h < 2; ++h) {
                int lr = wm * 32 + mf * 16 + h * 8 + g;
                float w = gsm[lr];
                #pragma unroll
                for (int nf = 0; nf < 4; ++nf) {
                    int col = wn * 32 + nf * 8 + tig * 2;
                    float2 nv = *(const float2*)swz(nbs, lr, col);
                    float s0 = sigm_fast(acc[mf][nf][2 * h]);
                    float s1 = sigm_fast(acc[mf][nf][2 * h + 1]);
                    csum[nf][0] += s0 * nv.x * w;
                    csum[nf][1] += s1 * nv.y * w;
                }
            }
        }
        #pragma unroll
        for (int off = 4; off <= 16; off <<= 1) {
            #pragma unroll
            for (int nf = 0; nf < 4; ++nf) {
                csum[nf][0] += __shfl_xor_sync(0xffffffffu, csum[nf][0], off);
                csum[nf][1] += __shfl_xor_sync(0xffffffffu, csum[nf][1], off);
            }
        }
        {
            int nf = g >> 1, j = g & 1;
            float v = csum[nf][j];
            float o = tsf_pref * v * (1.0f / 32.0f);
            out[(size_t)node * DDIM + ecol] = fmaxf(o, 0.f);
        }

        __syncthreads();   // all warps done with this stage before it is refilled
        s ^= 1;
    }
}

// ---------------- host: tensormap encode + launch ----------------
typedef CUresult (*EncFn)(CUtensorMap*, CUtensorMapDataType, cuuint32_t, void*,
                          const cuuint64_t*, const cuuint64_t*, const cuuint32_t*,
                          const cuuint32_t*, CUtensorMapInterleave, CUtensorMapSwizzle,
                          CUtensorMapL2promotion, CUtensorMapFloatOOBfill);

static EncFn get_encoder() {
    static EncFn fn = nullptr;
    if (!fn) {
        void* p = nullptr;
        cudaDriverEntryPointQueryResult st;
#if CUDART_VERSION >= 12050
        cudaGetDriverEntryPointByVersion("cuTensorMapEncodeTiled", &p, 12000,
                                         cudaEnableDefault, &st);
#else
        cudaGetDriverEntryPoint("cuTensorMapEncodeTiled", &p, cudaEnableDefault, &st);
#endif
        fn = (EncFn)p;
    }
    return fn;
}

static void make_map(CUtensorMap* m, const void* ptr) {
    cuuint64_t dims[2]    = {DDIM, (cuuint64_t)NNODES * KNEI};
    cuuint64_t strides[1] = {DDIM * 4};
    cuuint32_t box[2]     = {32, ROWS};
    cuuint32_t es[2]      = {1, 1};
    get_encoder()(m, CU_TENSOR_MAP_DATA_TYPE_FLOAT32, 2, (void*)ptr,
                  dims, strides, box, es,
                  CU_TENSOR_MAP_INTERLEAVE_NONE, CU_TENSOR_MAP_SWIZZLE_128B,
                  CU_TENSOR_MAP_L2_PROMOTION_L2_128B, CU_TENSOR_MAP_FLOAT_OOB_FILL_NONE);
}

extern "C" void kernel_launch(void* const* d_in, const int* in_sizes, int n_in,
                              void* d_out, int out_size)
{
    const float* self_feats   = (const float*)d_in[0];
    const float* self_vecs    = (const float*)d_in[1];
    const float* neigh_vecs   = (const float*)d_in[2];
    const float* link_vecs    = (const float*)d_in[3];
    const float* select_probs = (const float*)d_in[4];
    const float* gate_self_w  = (const float*)d_in[5];
    const float* gate_neigh_w = (const float*)d_in[6];
    const float* gate_link_w  = (const float*)d_in[7];
    const float* self_weights = (const float*)d_in[8];
    const float* link_weights = (const float*)d_in[9];
    float* out = (float*)d_out;

    CUtensorMap tml, tmn;
    make_map(&tml, link_vecs);
    make_map(&tmn, neigh_vecs);

    const int PRE_SMEM  = PRE_FLOATS * 4;    // 101888 B -> 2 CTAs/SM
    const int MAIN_SMEM = SMEM_FLOATS * 4;   // 202000 B
    cudaFuncSetAttribute(pre_kernel,  cudaFuncAttributeMaxDynamicSharedMemorySize, PRE_SMEM);
    cudaFuncSetAttribute(main_kernel, cudaFuncAttributeMaxDynamicSharedMemorySize, MAIN_SMEM);

    int sms = 148;
    cudaDeviceGetAttribute(&sms, cudaDevAttrMultiProcessorCount, 0);

    pre_kernel<<<(NNODES + PRE_CHUNK - 1) / PRE_CHUNK, 256, PRE_SMEM>>>(
        self_feats, self_vecs, gate_self_w, self_weights);
    main_kernel<<<sms, 256, MAIN_SMEM>>>(
        tml, tmn, select_probs, gate_neigh_w, gate_link_w, link_weights, out);
}